// round 3
// baseline (speedup 1.0000x reference)
#include <cuda_runtime.h>
#include <cstdint>
#include <math_constants.h>

#define DI __device__ __forceinline__

// ---------------- scratch ----------------
static __device__ float g_h1t[(size_t)256 * 131072]; // [F][B*N] f-major h1, tf32-rounded
static __device__ float g_At[256 * 64 * 64];         // [F][m][n] FULL adj (transposed), tf32-rounded
static __device__ float g_dT[64 * 256];              // [n][F] adj diagonal
static __device__ float g_Wc[256 * 512];             // [k][j] concat weights, tf32-rounded
static __device__ unsigned char g_mask[64 * 64];     // normalized mask

DI unsigned f2tf(float x) { unsigned u; asm("cvt.rna.tf32.f32 %0, %1;" : "=r"(u) : "f"(x)); return u; }
DI float f2tf_f(float x) { return __uint_as_float(f2tf(x)); }

// ---------------- prep: normalize mask dtype (bool8 / int32 / float32) ----------------
__global__ void prep_mask(const unsigned* __restrict__ raw) {
    __shared__ int s_gt1, s_f32;
    int tid = threadIdx.x;
    if (tid == 0) { s_gt1 = 0; s_f32 = 0; }
    __syncthreads();
    int gt1 = 0, f32 = 0;
    for (int i = tid; i < 1024; i += 256) {   // first 4096 bytes exist in every encoding
        unsigned w = raw[i];
        if (w == 0x3f800000u) f32 = 1;
        else if (w > 1u) gt1 = 1;
    }
    if (f32) atomicOr(&s_f32, 1);
    if (gt1) atomicOr(&s_gt1, 1);
    __syncthreads();
    bool isf = s_f32 != 0;
    bool isu8 = !isf && (s_gt1 != 0);
    for (int i = tid; i < 4096; i += 256) {
        unsigned char v;
        if (isf)       v = (((const float*)raw)[i] != 0.f);
        else if (isu8) v = (((const unsigned char*)raw)[i] != 0);
        else           v = (((const int*)raw)[i] != 0);
        g_mask[i] = v;
    }
}

// ---------------- prep: Wcat = [W0-W1 | W1], tf32-rounded ----------------
__global__ void prep_w(const float* __restrict__ W) {
    int t = blockIdx.x * 256 + threadIdx.x;      // 0..131071
    int k = t >> 9, j = t & 511;
    float v;
    if (j < 256) v = W[k * 256 + j] - W[65536 + k * 256 + j];
    else         v = W[65536 + k * 256 + (j - 256)];
    g_Wc[t] = f2tf_f(v);
}

// ---------------- prep: masked row softmax -> At (transposed, FULL incl. diag) + dT ----------------
// out = dT*(h0-h1) + adj@h1 + bias  requires At = full adj (diag kept):
//   adj@h1 = off@h1 + d*h1, cancelling the -d*h1 from the (W0-W1) epilogue term.
__global__ void prep_softmax(const float* __restrict__ e) {
    int wid = threadIdx.x >> 5, lane = threadIdx.x & 31;
    int idx = blockIdx.x * 8 + wid;              // 0..16383 = f*64+n
    int f = idx >> 6, n = idx & 63;
    const float* er = e + (size_t)idx * 64;      // e[f][n][*]
    int m1 = lane, m2 = lane + 32;
    bool k1 = g_mask[n * 64 + m1] != 0;
    bool k2 = g_mask[n * 64 + m2] != 0;
    float v1 = k1 ? er[m1] : -CUDART_INF_F;
    float v2 = k2 ? er[m2] : -CUDART_INF_F;
    float mx = fmaxf(v1, v2);
#pragma unroll
    for (int o = 16; o; o >>= 1) mx = fmaxf(mx, __shfl_xor_sync(0xffffffffu, mx, o));
    float p1 = k1 ? expf(v1 - mx) : 0.f;
    float p2 = k2 ? expf(v2 - mx) : 0.f;
    float s = p1 + p2;
#pragma unroll
    for (int o = 16; o; o >>= 1) s += __shfl_xor_sync(0xffffffffu, s, o);
    float inv = 1.f / s;
    float a1 = p1 * inv, a2 = p2 * inv;
    if (m1 == n) g_dT[n * 256 + f] = a1;
    if (m2 == n) g_dT[n * 256 + f] = a2;
    g_At[(f * 64 + m1) * 64 + n] = f2tf_f(a1);   // FULL adj — diagonal kept
    g_At[(f * 64 + m2) * 64 + n] = f2tf_f(a2);
}

// ---------------- GEMM: [131072,256] x [256,512], tf32 warp mma ----------------
// CTA tile 128x128, BK=32, 8 warps (2M x 4N), warp tile 64x32.
// Epilogue: cols <256 -> d_out = dT*acc + bias ; cols >=256 -> g_h1t (f-major, tf32-rounded)
#define GEMM_SMEM ((2 * 4608 + 2 * 4224) * 4)

__global__ __launch_bounds__(256) void gemm_xw(const float* __restrict__ x,
                                               const float* __restrict__ bias,
                                               float* __restrict__ out) {
    extern __shared__ float sm[];
    float* AsB = sm;              // 2 stages of [128][36]
    float* BsB = sm + 2 * 4608;   // 2 stages of [32][132]
    const int tid = threadIdx.x;
    const int wid = tid >> 5, lane = tid & 31;
    const int wm = wid >> 2, wn = wid & 3;
    const int g = lane >> 2, tt = lane & 3;
    const int Nblk = blockIdx.x;  // 0..3
    const int Mblk = blockIdx.y;  // 0..1023
    const float* xA = x + (size_t)Mblk * 128 * 256;
    const float* Wb = g_Wc + Nblk * 128;

    float acc[4][4][4];
#pragma unroll
    for (int a = 0; a < 4; a++)
#pragma unroll
        for (int b = 0; b < 4; b++)
#pragma unroll
            for (int c = 0; c < 4; c++) acc[a][b][c] = 0.f;

    float4 ra[4], rb[4];

    auto loadg = [&](int kb) {
#pragma unroll
        for (int i = 0; i < 4; i++) {
            int lin = tid + i * 256;
            ra[i] = *reinterpret_cast<const float4*>(xA + (size_t)(lin >> 3) * 256 + kb * 32 + ((lin & 7) << 2));
            rb[i] = *reinterpret_cast<const float4*>(Wb + (size_t)(kb * 32 + (lin >> 5)) * 512 + ((lin & 31) << 2));
        }
    };
    auto stores = [&](int st) {
        float* A = AsB + st * 4608;
        float* B = BsB + st * 4224;
#pragma unroll
        for (int i = 0; i < 4; i++) {
            int lin = tid + i * 256;
            float4 v = ra[i];
            v.x = f2tf_f(v.x); v.y = f2tf_f(v.y); v.z = f2tf_f(v.z); v.w = f2tf_f(v.w);
            *reinterpret_cast<float4*>(A + (lin >> 3) * 36 + ((lin & 7) << 2)) = v;
            *reinterpret_cast<float4*>(B + (lin >> 5) * 132 + ((lin & 31) << 2)) = rb[i];
        }
    };
    auto compute = [&](int st) {
        const float* A = AsB + st * 4608 + (wm * 64) * 36;
        const float* B = BsB + st * 4224 + wn * 32;
#pragma unroll
        for (int ks = 0; ks < 4; ks++) {
            int kk = ks * 8;
            unsigned af[4][4], bf[4][2];
#pragma unroll
            for (int mt = 0; mt < 4; mt++) {
                const float* Ap = A + (mt * 16 + g) * 36 + kk + tt;
                af[mt][0] = __float_as_uint(Ap[0]);
                af[mt][1] = __float_as_uint(Ap[8 * 36]);
                af[mt][2] = __float_as_uint(Ap[4]);
                af[mt][3] = __float_as_uint(Ap[8 * 36 + 4]);
            }
#pragma unroll
            for (int nt = 0; nt < 4; nt++) {
                const float* Bp = B + (kk + tt) * 132 + nt * 8 + g;
                bf[nt][0] = __float_as_uint(Bp[0]);
                bf[nt][1] = __float_as_uint(Bp[4 * 132]);
            }
#pragma unroll
            for (int mt = 0; mt < 4; mt++)
#pragma unroll
                for (int nt = 0; nt < 4; nt++) {
                    asm volatile(
                        "mma.sync.aligned.m16n8k8.row.col.f32.tf32.tf32.f32 "
                        "{%0,%1,%2,%3}, {%4,%5,%6,%7}, {%8,%9}, {%0,%1,%2,%3};\n"
                        : "+f"(acc[mt][nt][0]), "+f"(acc[mt][nt][1]),
                          "+f"(acc[mt][nt][2]), "+f"(acc[mt][nt][3])
                        : "r"(af[mt][0]), "r"(af[mt][1]), "r"(af[mt][2]), "r"(af[mt][3]),
                          "r"(bf[nt][0]), "r"(bf[nt][1]));
                }
        }
    };

    loadg(0);
    stores(0);
    __syncthreads();
#pragma unroll 1
    for (int kb = 0; kb < 8; kb++) {
        int cur = kb & 1;
        if (kb < 7) loadg(kb + 1);
        compute(cur);
        if (kb < 7) stores(cur ^ 1);
        __syncthreads();
    }

    int row0 = Mblk * 128 + wm * 64;
    int col0 = Nblk * 128 + wn * 32;
    if (Nblk < 2) {
#pragma unroll
        for (int mt = 0; mt < 4; mt++) {
#pragma unroll
            for (int nt = 0; nt < 4; nt++) {
                int j = col0 + nt * 8 + tt * 2;
                int r0 = row0 + mt * 16 + g;
                int r1 = r0 + 8;
                float2 bj = *reinterpret_cast<const float2*>(bias + j);
                float2 d0 = *reinterpret_cast<const float2*>(g_dT + (r0 & 63) * 256 + j);
                float2 d1 = *reinterpret_cast<const float2*>(g_dT + (r1 & 63) * 256 + j);
                float2 o0, o1;
                o0.x = d0.x * acc[mt][nt][0] + bj.x;
                o0.y = d0.y * acc[mt][nt][1] + bj.y;
                o1.x = d1.x * acc[mt][nt][2] + bj.x;
                o1.y = d1.y * acc[mt][nt][3] + bj.y;
                *reinterpret_cast<float2*>(out + (size_t)r0 * 256 + j) = o0;
                *reinterpret_cast<float2*>(out + (size_t)r1 * 256 + j) = o1;
            }
        }
    } else {
#pragma unroll
        for (int mt = 0; mt < 4; mt++) {
#pragma unroll
            for (int nt = 0; nt < 4; nt++) {
                int j = col0 + nt * 8 + tt * 2 - 256;
                int r0 = row0 + mt * 16 + g;
                int r1 = r0 + 8;
                g_h1t[(size_t)j * 131072 + r0]       = f2tf_f(acc[mt][nt][0]);
                g_h1t[(size_t)(j + 1) * 131072 + r0] = f2tf_f(acc[mt][nt][1]);
                g_h1t[(size_t)j * 131072 + r1]       = f2tf_f(acc[mt][nt][2]);
                g_h1t[(size_t)(j + 1) * 131072 + r1] = f2tf_f(acc[mt][nt][3]);
            }
        }
    }
}

// ---------------- mix: d_out[b,n,f] += sum_m At[f][m][n] * h1t[f][b*64+m] ----------------
// CTA: 8 channels (warp each) x 32-batch tile. Per warp: [32 x 64] += [32 x 64] @ [64 x 64]
#define MIX_SMEM ((8 * 32 * 68 + 8 * 16 * 132) * 4)

__global__ __launch_bounds__(256) void mix(float* __restrict__ out) {
    extern __shared__ float sm[];
    float* Hs = sm;                    // 8 x [32][68]
    float* Bs = sm + 8 * 32 * 68;      // 8 x [16][132] (K chunk)
    const int tid = threadIdx.x, w = tid >> 5, lane = tid & 31;
    const int g = lane >> 2, tt = lane & 3;
    const int mblk = blockIdx.x;       // 0..63 (batch tiles of 32)
    const int fblk = blockIdx.y;       // 0..31

    {   // load H: 8 channel regions, 2048 contiguous floats each
        const float* src = g_h1t + (size_t)fblk * 8 * 131072 + (size_t)mblk * 2048;
#pragma unroll
        for (int i = 0; i < 16; i++) {
            int lin = tid + i * 256;       // 0..4095 (float4 units)
            int fl = lin >> 9;
            int r = lin & 511;
            float4 v = *reinterpret_cast<const float4*>(src + (size_t)fl * 131072 + r * 4);
            int b = r >> 4, m = (r & 15) << 2;
            *reinterpret_cast<float4*>(Hs + fl * (32 * 68) + b * 68 + m) = v;
        }
    }

    float acc[2][8][4];
#pragma unroll
    for (int a = 0; a < 2; a++)
#pragma unroll
        for (int b = 0; b < 8; b++)
#pragma unroll
            for (int c = 0; c < 4; c++) acc[a][b][c] = 0.f;

#pragma unroll 1
    for (int c = 0; c < 4; c++) {
        int k0 = c * 16;
        __syncthreads();   // protect Bs reuse (and H visibility on c=0)
#pragma unroll
        for (int i = 0; i < 8; i++) {
            int lin = tid + i * 256;       // 0..2047 (float4 units)
            int fl = lin >> 8;
            int r = lin & 255;
            int k = r >> 4, n = (r & 15) << 2;
            float4 v = *reinterpret_cast<const float4*>(
                g_At + (size_t)(fblk * 8 + fl) * 4096 + (k0 + k) * 64 + n);
            *reinterpret_cast<float4*>(Bs + fl * (16 * 132) + k * 132 + n) = v;
        }
        __syncthreads();
        const float* Hw = Hs + w * (32 * 68);
        const float* Bw = Bs + w * (16 * 132);
#pragma unroll
        for (int ks = 0; ks < 2; ks++) {
            int kk = ks * 8;
            unsigned af[2][4], bf[8][2];
#pragma unroll
            for (int mt = 0; mt < 2; mt++) {
                const float* p = Hw + (mt * 16 + g) * 68 + k0 + kk + tt;
                af[mt][0] = __float_as_uint(p[0]);
                af[mt][1] = __float_as_uint(p[8 * 68]);
                af[mt][2] = __float_as_uint(p[4]);
                af[mt][3] = __float_as_uint(p[8 * 68 + 4]);
            }
#pragma unroll
            for (int nt = 0; nt < 8; nt++) {
                const float* p = Bw + (kk + tt) * 132 + nt * 8 + g;
                bf[nt][0] = __float_as_uint(p[0]);
                bf[nt][1] = __float_as_uint(p[4 * 132]);
            }
#pragma unroll
            for (int mt = 0; mt < 2; mt++)
#pragma unroll
                for (int nt = 0; nt < 8; nt++) {
                    asm volatile(
                        "mma.sync.aligned.m16n8k8.row.col.f32.tf32.tf32.f32 "
                        "{%0,%1,%2,%3}, {%4,%5,%6,%7}, {%8,%9}, {%0,%1,%2,%3};\n"
                        : "+f"(acc[mt][nt][0]), "+f"(acc[mt][nt][1]),
                          "+f"(acc[mt][nt][2]), "+f"(acc[mt][nt][3])
                        : "r"(af[mt][0]), "r"(af[mt][1]), "r"(af[mt][2]), "r"(af[mt][3]),
                          "r"(bf[nt][0]), "r"(bf[nt][1]));
                }
        }
    }

    __syncthreads();        // all Hs reads done; reuse as Cs [2048][8]
    float* Cs = sm;
#pragma unroll
    for (int mt = 0; mt < 2; mt++)
#pragma unroll
        for (int nt = 0; nt < 8; nt++) {
            int b0 = mt * 16 + g, n = nt * 8 + tt * 2;
            Cs[(b0 * 64 + n) * 8 + w]           = acc[mt][nt][0];
            Cs[(b0 * 64 + n + 1) * 8 + w]       = acc[mt][nt][1];
            Cs[((b0 + 8) * 64 + n) * 8 + w]     = acc[mt][nt][2];
            Cs[((b0 + 8) * 64 + n + 1) * 8 + w] = acc[mt][nt][3];
        }
    __syncthreads();

    float* obase = out + (size_t)mblk * 2048 * 256 + fblk * 8;
#pragma unroll
    for (int i = 0; i < 8; i++) {
        int Xl = tid + i * 256;
        float* op = obase + (size_t)Xl * 256;
        float4 o0 = *reinterpret_cast<float4*>(op);
        float4 o1 = *reinterpret_cast<float4*>(op + 4);
        const float* cc = Cs + Xl * 8;
        o0.x += cc[0]; o0.y += cc[1]; o0.z += cc[2]; o0.w += cc[3];
        o1.x += cc[4]; o1.y += cc[5]; o1.z += cc[6]; o1.w += cc[7];
        *reinterpret_cast<float4*>(op) = o0;
        *reinterpret_cast<float4*>(op + 4) = o1;
    }
}

// ---------------- launch ----------------
extern "C" void kernel_launch(void* const* d_in, const int* in_sizes, int n_in,
                              void* d_out, int out_size) {
    (void)in_sizes; (void)n_in; (void)out_size;
    const float* x = (const float*)d_in[0];
    const float* W = (const float*)d_in[1];
    const float* e = (const float*)d_in[2];
    const float* bias = (const float*)d_in[3];
    const unsigned* maskraw = (const unsigned*)d_in[4];
    float* out = (float*)d_out;

    cudaFuncSetAttribute(gemm_xw, cudaFuncAttributeMaxDynamicSharedMemorySize, GEMM_SMEM);
    cudaFuncSetAttribute(mix, cudaFuncAttributeMaxDynamicSharedMemorySize, MIX_SMEM);

    prep_mask<<<1, 256>>>(maskraw);
    prep_w<<<512, 256>>>(W);
    prep_softmax<<<2048, 256>>>(e);
    gemm_xw<<<dim3(4, 1024), 256, GEMM_SMEM>>>(x, bias, out);
    mix<<<dim3(64, 32), 256, MIX_SMEM>>>(out);
}

// round 4
// speedup vs baseline: 1.0369x; 1.0369x over previous
#include <cuda_runtime.h>
#include <cstdint>
#include <math_constants.h>

#define DI __device__ __forceinline__

// ---------------- scratch ----------------
static __device__ float g_h1t[(size_t)256 * 131072]; // [F][B*N] f-major h1, tf32-rounded
static __device__ float g_At[256 * 64 * 64];         // [F][m][n] FULL adj (transposed), tf32-rounded
static __device__ float g_dT[64 * 256];              // [n][F] adj diagonal
static __device__ float g_Wc[256 * 512];             // [k][j] concat weights, tf32-rounded
static __device__ unsigned char g_mask[64 * 64];     // normalized mask

DI unsigned f2tf(float x) { unsigned u; asm("cvt.rna.tf32.f32 %0, %1;" : "=r"(u) : "f"(x)); return u; }
DI float f2tf_f(float x) { return __uint_as_float(f2tf(x)); }

// ---------------- prep: normalize mask dtype (bool8 / int32 / float32) ----------------
__global__ void prep_mask(const unsigned* __restrict__ raw) {
    __shared__ int s_gt1, s_f32;
    int tid = threadIdx.x;
    if (tid == 0) { s_gt1 = 0; s_f32 = 0; }
    __syncthreads();
    int gt1 = 0, f32 = 0;
    for (int i = tid; i < 1024; i += 256) {
        unsigned w = raw[i];
        if (w == 0x3f800000u) f32 = 1;
        else if (w > 1u) gt1 = 1;
    }
    if (f32) atomicOr(&s_f32, 1);
    if (gt1) atomicOr(&s_gt1, 1);
    __syncthreads();
    bool isf = s_f32 != 0;
    bool isu8 = !isf && (s_gt1 != 0);
    for (int i = tid; i < 4096; i += 256) {
        unsigned char v;
        if (isf)       v = (((const float*)raw)[i] != 0.f);
        else if (isu8) v = (((const unsigned char*)raw)[i] != 0);
        else           v = (((const int*)raw)[i] != 0);
        g_mask[i] = v;
    }
}

// ---------------- prep: Wcat = [W0-W1 | W1], tf32-rounded ----------------
__global__ void prep_w(const float* __restrict__ W) {
    int t = blockIdx.x * 256 + threadIdx.x;
    int k = t >> 9, j = t & 511;
    float v;
    if (j < 256) v = W[k * 256 + j] - W[65536 + k * 256 + j];
    else         v = W[65536 + k * 256 + (j - 256)];
    g_Wc[t] = f2tf_f(v);
}

// ---------------- prep: masked row softmax -> At (FULL adj, transposed) + dT ----------------
__global__ void prep_softmax(const float* __restrict__ e) {
    int wid = threadIdx.x >> 5, lane = threadIdx.x & 31;
    int idx = blockIdx.x * 8 + wid;              // f*64+n
    int f = idx >> 6, n = idx & 63;
    const float* er = e + (size_t)idx * 64;
    int m1 = lane, m2 = lane + 32;
    bool k1 = g_mask[n * 64 + m1] != 0;
    bool k2 = g_mask[n * 64 + m2] != 0;
    float v1 = k1 ? er[m1] : -CUDART_INF_F;
    float v2 = k2 ? er[m2] : -CUDART_INF_F;
    float mx = fmaxf(v1, v2);
#pragma unroll
    for (int o = 16; o; o >>= 1) mx = fmaxf(mx, __shfl_xor_sync(0xffffffffu, mx, o));
    float p1 = k1 ? expf(v1 - mx) : 0.f;
    float p2 = k2 ? expf(v2 - mx) : 0.f;
    float s = p1 + p2;
#pragma unroll
    for (int o = 16; o; o >>= 1) s += __shfl_xor_sync(0xffffffffu, s, o);
    float inv = 1.f / s;
    float a1 = p1 * inv, a2 = p2 * inv;
    if (m1 == n) g_dT[n * 256 + f] = a1;
    if (m2 == n) g_dT[n * 256 + f] = a2;
    g_At[(f * 64 + m1) * 64 + n] = f2tf_f(a1);
    g_At[(f * 64 + m2) * 64 + n] = f2tf_f(a2);
}

// ---------------- GEMM: [131072,256] x [256,512], tf32 warp mma ----------------
#define GEMM_SMEM ((2 * 4608 + 2 * 4224) * 4)

__global__ __launch_bounds__(256) void gemm_xw(const float* __restrict__ x,
                                               const float* __restrict__ bias,
                                               float* __restrict__ out) {
    extern __shared__ float sm[];
    float* AsB = sm;              // 2 stages of [128][36]
    float* BsB = sm + 2 * 4608;   // 2 stages of [32][132]
    const int tid = threadIdx.x;
    const int wid = tid >> 5, lane = tid & 31;
    const int wm = wid >> 2, wn = wid & 3;
    const int g = lane >> 2, tt = lane & 3;
    const int Nblk = blockIdx.x;
    const int Mblk = blockIdx.y;
    const float* xA = x + (size_t)Mblk * 128 * 256;
    const float* Wb = g_Wc + Nblk * 128;

    float acc[4][4][4];
#pragma unroll
    for (int a = 0; a < 4; a++)
#pragma unroll
        for (int b = 0; b < 4; b++)
#pragma unroll
            for (int c = 0; c < 4; c++) acc[a][b][c] = 0.f;

    float4 ra[4], rb[4];

    auto loadg = [&](int kb) {
#pragma unroll
        for (int i = 0; i < 4; i++) {
            int lin = tid + i * 256;
            ra[i] = *reinterpret_cast<const float4*>(xA + (size_t)(lin >> 3) * 256 + kb * 32 + ((lin & 7) << 2));
            rb[i] = *reinterpret_cast<const float4*>(Wb + (size_t)(kb * 32 + (lin >> 5)) * 512 + ((lin & 31) << 2));
        }
    };
    auto stores = [&](int st) {
        float* A = AsB + st * 4608;
        float* B = BsB + st * 4224;
#pragma unroll
        for (int i = 0; i < 4; i++) {
            int lin = tid + i * 256;
            float4 v = ra[i];
            v.x = f2tf_f(v.x); v.y = f2tf_f(v.y); v.z = f2tf_f(v.z); v.w = f2tf_f(v.w);
            *reinterpret_cast<float4*>(A + (lin >> 3) * 36 + ((lin & 7) << 2)) = v;
            *reinterpret_cast<float4*>(B + (lin >> 5) * 132 + ((lin & 31) << 2)) = rb[i];
        }
    };
    auto compute = [&](int st) {
        const float* A = AsB + st * 4608 + (wm * 64) * 36;
        const float* B = BsB + st * 4224 + wn * 32;
#pragma unroll
        for (int ks = 0; ks < 4; ks++) {
            int kk = ks * 8;
            unsigned af[4][4], bf[4][2];
#pragma unroll
            for (int mt = 0; mt < 4; mt++) {
                const float* Ap = A + (mt * 16 + g) * 36 + kk + tt;
                af[mt][0] = __float_as_uint(Ap[0]);
                af[mt][1] = __float_as_uint(Ap[8 * 36]);
                af[mt][2] = __float_as_uint(Ap[4]);
                af[mt][3] = __float_as_uint(Ap[8 * 36 + 4]);
            }
#pragma unroll
            for (int nt = 0; nt < 4; nt++) {
                const float* Bp = B + (kk + tt) * 132 + nt * 8 + g;
                bf[nt][0] = __float_as_uint(Bp[0]);
                bf[nt][1] = __float_as_uint(Bp[4 * 132]);
            }
#pragma unroll
            for (int mt = 0; mt < 4; mt++)
#pragma unroll
                for (int nt = 0; nt < 4; nt++) {
                    asm volatile(
                        "mma.sync.aligned.m16n8k8.row.col.f32.tf32.tf32.f32 "
                        "{%0,%1,%2,%3}, {%4,%5,%6,%7}, {%8,%9}, {%0,%1,%2,%3};\n"
                        : "+f"(acc[mt][nt][0]), "+f"(acc[mt][nt][1]),
                          "+f"(acc[mt][nt][2]), "+f"(acc[mt][nt][3])
                        : "r"(af[mt][0]), "r"(af[mt][1]), "r"(af[mt][2]), "r"(af[mt][3]),
                          "r"(bf[nt][0]), "r"(bf[nt][1]));
                }
        }
    };

    loadg(0);
    stores(0);
    __syncthreads();
#pragma unroll 1
    for (int kb = 0; kb < 8; kb++) {
        int cur = kb & 1;
        if (kb < 7) loadg(kb + 1);
        compute(cur);
        if (kb < 7) stores(cur ^ 1);
        __syncthreads();
    }

    int row0 = Mblk * 128 + wm * 64;
    int col0 = Nblk * 128 + wn * 32;
    if (Nblk < 2) {
#pragma unroll
        for (int mt = 0; mt < 4; mt++) {
#pragma unroll
            for (int nt = 0; nt < 4; nt++) {
                int j = col0 + nt * 8 + tt * 2;
                int r0 = row0 + mt * 16 + g;
                int r1 = r0 + 8;
                float2 bj = *reinterpret_cast<const float2*>(bias + j);
                float2 d0 = *reinterpret_cast<const float2*>(g_dT + (r0 & 63) * 256 + j);
                float2 d1 = *reinterpret_cast<const float2*>(g_dT + (r1 & 63) * 256 + j);
                float2 o0, o1;
                o0.x = d0.x * acc[mt][nt][0] + bj.x;
                o0.y = d0.y * acc[mt][nt][1] + bj.y;
                o1.x = d1.x * acc[mt][nt][2] + bj.x;
                o1.y = d1.y * acc[mt][nt][3] + bj.y;
                *reinterpret_cast<float2*>(out + (size_t)r0 * 256 + j) = o0;
                *reinterpret_cast<float2*>(out + (size_t)r1 * 256 + j) = o1;
            }
        }
    } else {
#pragma unroll
        for (int mt = 0; mt < 4; mt++) {
#pragma unroll
            for (int nt = 0; nt < 4; nt++) {
                int j = col0 + nt * 8 + tt * 2 - 256;
                int r0 = row0 + mt * 16 + g;
                int r1 = r0 + 8;
                g_h1t[(size_t)j * 131072 + r0]       = f2tf_f(acc[mt][nt][0]);
                g_h1t[(size_t)(j + 1) * 131072 + r0] = f2tf_f(acc[mt][nt][1]);
                g_h1t[(size_t)j * 131072 + r1]       = f2tf_f(acc[mt][nt][2]);
                g_h1t[(size_t)(j + 1) * 131072 + r1] = f2tf_f(acc[mt][nt][3]);
            }
        }
    }
}

// ---------------- mix v2: d_out[b,n,f] += sum_m At[f][m][n] * h1t[f][b*64+m] ----------------
// Per CTA: 8 channels (warp each) x 32-batch tile. Warp: C[32,64] = H[32,64] @ A_f[64,64].
// H staged once in smem (coalesced); A_f fragments loaded straight from L2 (4MB resident).
// No per-chunk block barriers; 69.6KB smem -> 2 CTAs/SM.
#define MIX_SMEM (8 * 32 * 68 * 4)

__global__ __launch_bounds__(256) void mix(float* __restrict__ out) {
    extern __shared__ float sm[];
    float* Hs = sm;                    // 8 x [32][68]
    const int tid = threadIdx.x, w = tid >> 5, lane = tid & 31;
    const int g = lane >> 2, tt = lane & 3;
    const int mblk = blockIdx.x;       // 0..63 (batch tiles of 32)
    const int fblk = blockIdx.y;       // 0..31

    {   // load H: 8 channel regions, 2048 contiguous floats each (fully coalesced)
        const float* src = g_h1t + (size_t)fblk * 8 * 131072 + (size_t)mblk * 2048;
#pragma unroll
        for (int i = 0; i < 16; i++) {
            int lin = tid + i * 256;       // 0..4095 (float4 units)
            int fl = lin >> 9;
            int r = lin & 511;
            float4 v = *reinterpret_cast<const float4*>(src + (size_t)fl * 131072 + r * 4);
            int b = r >> 4, m = (r & 15) << 2;
            *reinterpret_cast<float4*>(Hs + fl * (32 * 68) + b * 68 + m) = v;
        }
    }
    __syncthreads();

    float acc[2][8][4];
#pragma unroll
    for (int a = 0; a < 2; a++)
#pragma unroll
        for (int b = 0; b < 8; b++)
#pragma unroll
            for (int c = 0; c < 4; c++) acc[a][b][c] = 0.f;

    const float* Hw = Hs + w * (32 * 68);
    const float* Aw = g_At + (size_t)(fblk * 8 + w) * 4096;   // A_f[m][n]

#pragma unroll 2
    for (int ks = 0; ks < 8; ks++) {
        int kk = ks * 8;
        unsigned af[2][4], bf[8][2];
#pragma unroll
        for (int mt = 0; mt < 2; mt++) {
            const float* p = Hw + (mt * 16 + g) * 68 + kk + tt;
            af[mt][0] = __float_as_uint(p[0]);
            af[mt][1] = __float_as_uint(p[8 * 68]);
            af[mt][2] = __float_as_uint(p[4]);
            af[mt][3] = __float_as_uint(p[8 * 68 + 4]);
        }
#pragma unroll
        for (int nt = 0; nt < 8; nt++) {
            const float* q = Aw + (kk + tt) * 64 + nt * 8 + g;   // B[k][n], k=m
            bf[nt][0] = __float_as_uint(__ldg(q));
            bf[nt][1] = __float_as_uint(__ldg(q + 4 * 64));
        }
#pragma unroll
        for (int mt = 0; mt < 2; mt++)
#pragma unroll
            for (int nt = 0; nt < 8; nt++) {
                asm volatile(
                    "mma.sync.aligned.m16n8k8.row.col.f32.tf32.tf32.f32 "
                    "{%0,%1,%2,%3}, {%4,%5,%6,%7}, {%8,%9}, {%0,%1,%2,%3};\n"
                    : "+f"(acc[mt][nt][0]), "+f"(acc[mt][nt][1]),
                      "+f"(acc[mt][nt][2]), "+f"(acc[mt][nt][3])
                    : "r"(af[mt][0]), "r"(af[mt][1]), "r"(af[mt][2]), "r"(af[mt][3]),
                      "r"(bf[nt][0]), "r"(bf[nt][1]));
            }
    }

    __syncthreads();        // all Hs reads done; reuse as Cs [2048][8]
    float* Cs = sm;
#pragma unroll
    for (int mt = 0; mt < 2; mt++)
#pragma unroll
        for (int nt = 0; nt < 8; nt++) {
            int b0 = mt * 16 + g, n = nt * 8 + tt * 2;
            Cs[(b0 * 64 + n) * 8 + w]           = acc[mt][nt][0];
            Cs[(b0 * 64 + n + 1) * 8 + w]       = acc[mt][nt][1];
            Cs[((b0 + 8) * 64 + n) * 8 + w]     = acc[mt][nt][2];
            Cs[((b0 + 8) * 64 + n + 1) * 8 + w] = acc[mt][nt][3];
        }
    __syncthreads();

    float* obase = out + (size_t)mblk * 2048 * 256 + fblk * 8;
#pragma unroll
    for (int i = 0; i < 8; i++) {
        int Xl = tid + i * 256;
        float* op = obase + (size_t)Xl * 256;
        float4 o0 = *reinterpret_cast<float4*>(op);
        float4 o1 = *reinterpret_cast<float4*>(op + 4);
        const float* cc = Cs + Xl * 8;
        o0.x += cc[0]; o0.y += cc[1]; o0.z += cc[2]; o0.w += cc[3];
        o1.x += cc[4]; o1.y += cc[5]; o1.z += cc[6]; o1.w += cc[7];
        *reinterpret_cast<float4*>(op) = o0;
        *reinterpret_cast<float4*>(op + 4) = o1;
    }
}

// ---------------- launch ----------------
extern "C" void kernel_launch(void* const* d_in, const int* in_sizes, int n_in,
                              void* d_out, int out_size) {
    (void)in_sizes; (void)n_in; (void)out_size;
    const float* x = (const float*)d_in[0];
    const float* W = (const float*)d_in[1];
    const float* e = (const float*)d_in[2];
    const float* bias = (const float*)d_in[3];
    const unsigned* maskraw = (const unsigned*)d_in[4];
    float* out = (float*)d_out;

    cudaFuncSetAttribute(gemm_xw, cudaFuncAttributeMaxDynamicSharedMemorySize, GEMM_SMEM);
    cudaFuncSetAttribute(mix, cudaFuncAttributeMaxDynamicSharedMemorySize, MIX_SMEM);

    prep_mask<<<1, 256>>>(maskraw);
    prep_w<<<512, 256>>>(W);
    prep_softmax<<<2048, 256>>>(e);
    gemm_xw<<<dim3(4, 1024), 256, GEMM_SMEM>>>(x, bias, out);
    mix<<<dim3(64, 32), 256, MIX_SMEM>>>(out);
}